// round 11
// baseline (speedup 1.0000x reference)
#include <cuda_runtime.h>
#include <cuda_bf16.h>
#include <cstdint>

#define D_DIM 512
#define D_VEC 128   // D_DIM / 4 (float4 stride per row)
#define MAX_NODES 100000
#define M_PAD 100096          // 782 * 128 (padded row count for GEMM tiles)
#define M_TILES 782

// ---------------------------------------------------------------------------
// Scratch (allocation-free rule: device globals are allowed)
// ---------------------------------------------------------------------------
__device__ float g_buf0[(size_t)MAX_NODES * D_DIM];
__device__ float g_buf1[(size_t)MAX_NODES * D_DIM];
__device__ int   g_rowstart[MAX_NODES + 1];
// bf16 hi/lo splits, stored as uint4 for guaranteed 16B alignment
__device__ uint4 g_ahi4[(size_t)M_PAD * 64];     // A:   [M_PAD][512] bf16
__device__ uint4 g_alo4[(size_t)M_PAD * 64];
__device__ uint4 g_bhi4[D_DIM * 64];             // W^T: [n][k] bf16
__device__ uint4 g_blo4[D_DIM * 64];

// ---------------------------------------------------------------------------
// PTX helpers (sm_103-safe: HMMA mma.sync + cp.async only, no tcgen05)
// ---------------------------------------------------------------------------
__device__ __forceinline__ uint32_t smem_to_u32(const void* p) {
    uint32_t a;
    asm("{ .reg .u64 t; cvta.to.shared.u64 t, %1; cvt.u32.u64 %0, t; }"
        : "=r"(a) : "l"(p));
    return a;
}
__device__ __forceinline__ void cp16(uint32_t s, const void* g) {
    asm volatile("cp.async.cg.shared.global [%0], [%1], 16;"
                 :: "r"(s), "l"(g) : "memory");
}
#define CP_COMMIT() asm volatile("cp.async.commit_group;" ::: "memory")
#define CP_WAIT(n)  asm volatile("cp.async.wait_group %0;" :: "n"(n) : "memory")

__device__ __forceinline__ uint32_t lds32(uint32_t a) {
    uint32_t v;
    asm("ld.shared.b32 %0, [%1];" : "=r"(v) : "r"(a));
    return v;
}
__device__ __forceinline__ void mma16816(float* d, const uint32_t* a,
                                         const uint32_t* b) {
    asm volatile(
        "mma.sync.aligned.m16n8k16.row.col.f32.bf16.bf16.f32 "
        "{%0,%1,%2,%3}, {%4,%5,%6,%7}, {%8,%9}, {%0,%1,%2,%3};"
        : "+f"(d[0]), "+f"(d[1]), "+f"(d[2]), "+f"(d[3])
        : "r"(a[0]), "r"(a[1]), "r"(a[2]), "r"(a[3]),
          "r"(b[0]), "r"(b[1]));
}

// ---------------------------------------------------------------------------
// Conversions: fp32 -> (bf16 hi, bf16 lo) splits
// ---------------------------------------------------------------------------
__global__ void convert_a_kernel(const float4* __restrict__ A, int m)
{
    size_t i = (size_t)blockIdx.x * blockDim.x + threadIdx.x;  // float4 index
    if (i >= (size_t)M_PAD * (D_DIM / 4)) return;
    size_t row = i / (D_DIM / 4);
    float4 v = make_float4(0.f, 0.f, 0.f, 0.f);
    if (row < (size_t)m) v = A[i];
    __nv_bfloat16 hx = __float2bfloat16_rn(v.x);
    __nv_bfloat16 hy = __float2bfloat16_rn(v.y);
    __nv_bfloat16 hz = __float2bfloat16_rn(v.z);
    __nv_bfloat16 hw = __float2bfloat16_rn(v.w);
    ushort4 hi, lo;
    hi.x = __bfloat16_as_ushort(hx);
    hi.y = __bfloat16_as_ushort(hy);
    hi.z = __bfloat16_as_ushort(hz);
    hi.w = __bfloat16_as_ushort(hw);
    lo.x = __bfloat16_as_ushort(__float2bfloat16_rn(v.x - __bfloat162float(hx)));
    lo.y = __bfloat16_as_ushort(__float2bfloat16_rn(v.y - __bfloat162float(hy)));
    lo.z = __bfloat16_as_ushort(__float2bfloat16_rn(v.z - __bfloat162float(hz)));
    lo.w = __bfloat16_as_ushort(__float2bfloat16_rn(v.w - __bfloat162float(hw)));
    reinterpret_cast<ushort4*>(g_ahi4)[i] = hi;
    reinterpret_cast<ushort4*>(g_alo4)[i] = lo;
}

__global__ void convert_w_kernel(const float* __restrict__ W)
{
    int i = blockIdx.x * blockDim.x + threadIdx.x;   // over k*512+n
    if (i >= D_DIM * D_DIM) return;
    int k = i / D_DIM, n = i % D_DIM;
    float w = W[i];
    __nv_bfloat16 h = __float2bfloat16_rn(w);
    __nv_bfloat16 l = __float2bfloat16_rn(w - __bfloat162float(h));
    reinterpret_cast<__nv_bfloat16*>(g_bhi4)[n * D_DIM + k] = h;
    reinterpret_cast<__nv_bfloat16*>(g_blo4)[n * D_DIM + k] = l;
}

// ---------------------------------------------------------------------------
// HMMA GEMM: C = Ahi·Bhi + Ahi·Blo + Alo·Bhi (fp32 accum) — unchanged from R9
// ---------------------------------------------------------------------------
#define BK 32
#define NCHUNKS (D_DIM / BK)   // 16
#define ROWB 80                // 32 bf16 (64B) + 16B pad
#define MATB (128 * ROWB)
#define AHI_OFF 0
#define ALO_OFF (1 * MATB)
#define BHI_OFF (2 * MATB)
#define BLO_OFF (3 * MATB)
#define BUFB (4 * MATB)
#define GEMM_SMEM (2 * BUFB)   // 81920 B

__device__ __forceinline__ void load_chunk(uint32_t buf, int bm, int bn,
                                           int kc, int tid)
{
    #pragma unroll
    for (int p = 0; p < 2; p++) {
        int u = tid + p * 256;
        int row = u >> 2, seg = u & 3;
        uint32_t so = buf + row * ROWB + seg * 16;
        size_t ga = (size_t)(bm + row) * 64 + kc * 4 + seg;
        size_t gb = (size_t)(bn + row) * 64 + kc * 4 + seg;
        cp16(so + AHI_OFF, &g_ahi4[ga]);
        cp16(so + ALO_OFF, &g_alo4[ga]);
        cp16(so + BHI_OFF, &g_bhi4[gb]);
        cp16(so + BLO_OFF, &g_blo4[gb]);
    }
}

__global__ __launch_bounds__(256, 2) void gemm_mma_kernel(
    float* __restrict__ C, int m)
{
    extern __shared__ char smem[];
    uint32_t sb = smem_to_u32(smem);
    int tid = threadIdx.x;
    int wid = tid >> 5, lane = tid & 31;
    int wm = wid & 1, wn = wid >> 1;
    int g = lane >> 2, tig = lane & 3;
    int bn = blockIdx.x * 128;
    int bm = blockIdx.y * 128;

    float acc[4][4][4];
    #pragma unroll
    for (int i = 0; i < 4; i++)
        #pragma unroll
        for (int j = 0; j < 4; j++)
            #pragma unroll
            for (int r = 0; r < 4; r++) acc[i][j][r] = 0.f;

    load_chunk(sb, bm, bn, 0, tid);
    CP_COMMIT();

    for (int kc = 0; kc < NCHUNKS; kc++) {
        uint32_t cur = sb + (kc & 1) * BUFB;
        if (kc + 1 < NCHUNKS) {
            load_chunk(sb + ((kc + 1) & 1) * BUFB, bm, bn, kc + 1, tid);
            CP_COMMIT();
            CP_WAIT(1);
        } else {
            CP_WAIT(0);
        }
        __syncthreads();

        #pragma unroll
        for (int term = 0; term < 3; term++) {
            uint32_t abase = cur + (term == 2 ? ALO_OFF : AHI_OFF);
            uint32_t bbase = cur + (term == 1 ? BLO_OFF : BHI_OFF);
            #pragma unroll
            for (int ks = 0; ks < 2; ks++) {
                uint32_t kb = (uint32_t)(ks * 32 + tig * 4);
                uint32_t afr[4][4], bfr[4][2];
                #pragma unroll
                for (int mi = 0; mi < 4; mi++) {
                    uint32_t r0 = abase + (uint32_t)((wm * 64 + mi * 16 + g) * ROWB) + kb;
                    uint32_t r1 = r0 + 8 * ROWB;
                    afr[mi][0] = lds32(r0);
                    afr[mi][1] = lds32(r1);
                    afr[mi][2] = lds32(r0 + 16);
                    afr[mi][3] = lds32(r1 + 16);
                }
                #pragma unroll
                for (int nj = 0; nj < 4; nj++) {
                    uint32_t n0 = bbase + (uint32_t)((wn * 32 + nj * 8 + g) * ROWB) + kb;
                    bfr[nj][0] = lds32(n0);
                    bfr[nj][1] = lds32(n0 + 16);
                }
                #pragma unroll
                for (int mi = 0; mi < 4; mi++)
                    #pragma unroll
                    for (int nj = 0; nj < 4; nj++)
                        mma16816(acc[mi][nj], afr[mi], bfr[nj]);
            }
        }
        __syncthreads();
    }

    #pragma unroll
    for (int mi = 0; mi < 4; mi++) {
        int r0 = bm + wm * 64 + mi * 16 + g;
        int r1 = r0 + 8;
        #pragma unroll
        for (int nj = 0; nj < 4; nj++) {
            int col = bn + wn * 32 + nj * 8 + tig * 2;
            if (r0 < m)
                *reinterpret_cast<float2*>(&C[(size_t)r0 * D_DIM + col]) =
                    make_float2(acc[mi][nj][0], acc[mi][nj][1]);
            if (r1 < m)
                *reinterpret_cast<float2*>(&C[(size_t)r1 * D_DIM + col]) =
                    make_float2(acc[mi][nj][2], acc[mi][nj][3]);
        }
    }
}

// ---------------------------------------------------------------------------
// Build row_start[] from sorted edge_dst via lower_bound binary search
// ---------------------------------------------------------------------------
__global__ void build_rowptr_kernel(const int* __restrict__ edge_dst,
                                    int n_edges, int n_nodes)
{
    int n = blockIdx.x * blockDim.x + threadIdx.x;
    if (n > n_nodes) return;
    int lo = 0, hi = n_edges;
    while (lo < hi) {
        int mid = (lo + hi) >> 1;
        if (edge_dst[mid] < n) lo = mid + 1; else hi = mid;
    }
    g_rowstart[n] = lo;
}

// ---------------------------------------------------------------------------
// SpMM quarter-column kernel v2: one warp per node, 32 float4 cols.
// Edge metadata loaded as int4/float4 broadcasts (4 LDG per 8 edges instead
// of 16 scalar LDGs) -> cuts warp LDG count per 8 edges from 24 to 12.
// Requires 4-alignment of the edge index; handled by a scalar pre-loop.
// FINAL hop stores __stwt (bypass L2); intermediate hops write-back so the
// next hop's gather hits L2.
// ---------------------------------------------------------------------------
__device__ __forceinline__ void spmm_fma(float4& acc, float w, const float4& r) {
    acc.x += w * r.x;
    acc.y += w * r.y;
    acc.z += w * r.z;
    acc.w += w * r.w;
}

template <int FINAL>
__global__ __launch_bounds__(64) void spmm_q_kernel(
    const float4* __restrict__ x,
    const int*    __restrict__ edge_src,
    const float*  __restrict__ edge_weight,
    float4*       __restrict__ out,
    int col_off,     // float4 units: 0,32,64,96
    int n_nodes)
{
    int warp = threadIdx.x >> 5;
    int n = blockIdx.x * 2 + warp;
    if (n >= n_nodes) return;
    int lane = threadIdx.x & 31;
    int c = col_off + lane;
    int s = g_rowstart[n];
    int e = g_rowstart[n + 1];

    const int4*   es4 = reinterpret_cast<const int4*>(edge_src);
    const float4* ew4 = reinterpret_cast<const float4*>(edge_weight);

    float4 acc = make_float4(0.f, 0.f, 0.f, 0.f);

    int i = s;
    // scalar pre-loop to 4-align i (at most 3 iterations)
    int lim = (s + 3) & ~3;
    if (lim > e) lim = e;
    for (; i < lim; i++) {
        int   sn = __ldcs(&edge_src[i]);
        float wt = __ldcs(&edge_weight[i]);
        float4 r = __ldg(&x[(size_t)sn * D_VEC + c]);
        spmm_fma(acc, wt, r);
    }
    // main loop: 8 edges, vectorized metadata (2x int4 + 2x float4 broadcast)
    for (; i + 8 <= e; i += 8) {
        int q = i >> 2;
        int4   sA = __ldcs(&es4[q]);
        int4   sB = __ldcs(&es4[q + 1]);
        float4 wA = __ldcs(&ew4[q]);
        float4 wB = __ldcs(&ew4[q + 1]);
        float4 r0 = __ldg(&x[(size_t)sA.x * D_VEC + c]);
        float4 r1 = __ldg(&x[(size_t)sA.y * D_VEC + c]);
        float4 r2 = __ldg(&x[(size_t)sA.z * D_VEC + c]);
        float4 r3 = __ldg(&x[(size_t)sA.w * D_VEC + c]);
        float4 r4 = __ldg(&x[(size_t)sB.x * D_VEC + c]);
        float4 r5 = __ldg(&x[(size_t)sB.y * D_VEC + c]);
        float4 r6 = __ldg(&x[(size_t)sB.z * D_VEC + c]);
        float4 r7 = __ldg(&x[(size_t)sB.w * D_VEC + c]);
        spmm_fma(acc, wA.x, r0);
        spmm_fma(acc, wA.y, r1);
        spmm_fma(acc, wA.z, r2);
        spmm_fma(acc, wA.w, r3);
        spmm_fma(acc, wB.x, r4);
        spmm_fma(acc, wB.y, r5);
        spmm_fma(acc, wB.z, r6);
        spmm_fma(acc, wB.w, r7);
    }
    // 4-edge step
    if (i + 4 <= e) {
        int q = i >> 2;
        int4   sA = __ldcs(&es4[q]);
        float4 wA = __ldcs(&ew4[q]);
        float4 r0 = __ldg(&x[(size_t)sA.x * D_VEC + c]);
        float4 r1 = __ldg(&x[(size_t)sA.y * D_VEC + c]);
        float4 r2 = __ldg(&x[(size_t)sA.z * D_VEC + c]);
        float4 r3 = __ldg(&x[(size_t)sA.w * D_VEC + c]);
        spmm_fma(acc, wA.x, r0);
        spmm_fma(acc, wA.y, r1);
        spmm_fma(acc, wA.z, r2);
        spmm_fma(acc, wA.w, r3);
        i += 4;
    }
    // scalar tail (at most 3)
    for (; i < e; i++) {
        int   sn = __ldcs(&edge_src[i]);
        float wt = __ldcs(&edge_weight[i]);
        float4 r = __ldg(&x[(size_t)sn * D_VEC + c]);
        spmm_fma(acc, wt, r);
    }

    if (FINAL)
        __stwt(&out[(size_t)n * D_VEC + c], acc);
    else
        out[(size_t)n * D_VEC + c] = acc;
}

// ---------------------------------------------------------------------------
// Launch
// ---------------------------------------------------------------------------
extern "C" void kernel_launch(void* const* d_in, const int* in_sizes, int n_in,
                              void* d_out, int out_size)
{
    const float* features    = (const float*)d_in[0];
    const float* weight      = (const float*)d_in[1];
    const int*   edge_src    = (const int*)  d_in[2];
    const int*   edge_dst    = (const int*)  d_in[3];
    const float* edge_weight = (const float*)d_in[4];
    // d_in[5] = times (fixed at 3); sync read forbidden under graph capture.

    int n_nodes = in_sizes[0] / D_DIM;
    int n_edges = in_sizes[2];
    float* out = (float*)d_out;

    float* buf0 = nullptr;
    float* buf1 = nullptr;
    cudaGetSymbolAddress((void**)&buf0, g_buf0);
    cudaGetSymbolAddress((void**)&buf1, g_buf1);

    cudaFuncSetAttribute(gemm_mma_kernel,
                         cudaFuncAttributeMaxDynamicSharedMemorySize, GEMM_SMEM);

    // 1) bf16 hi/lo splits of features and W^T
    {
        size_t nv = (size_t)M_PAD * (D_DIM / 4);
        convert_a_kernel<<<(unsigned)((nv + 255) / 256), 256>>>(
            (const float4*)features, n_nodes);
        convert_w_kernel<<<(D_DIM * D_DIM + 255) / 256, 256>>>(weight);
    }

    // 2) support = features @ W via HMMA (3-term bf16 split) -> buf0
    dim3 gemm_grid(D_DIM / 128, M_TILES);
    gemm_mma_kernel<<<gemm_grid, 256, GEMM_SMEM>>>(buf0, n_nodes);

    // 3) CSR row pointers from sorted edge_dst
    build_rowptr_kernel<<<(n_nodes + 1 + 255) / 256, 256>>>(edge_dst, n_edges, n_nodes);

    // 4) 3-hop chain per column quarter (51 MB slices -> L2-resident chaining)
    int spmm_grid = (n_nodes + 1) / 2;
    for (int q = 0; q < 4; q++) {
        int co = q * 32;   // float4 column offset
        spmm_q_kernel<0><<<spmm_grid, 64>>>((const float4*)buf0, edge_src,
                                            edge_weight, (float4*)buf1, co, n_nodes);
        spmm_q_kernel<0><<<spmm_grid, 64>>>((const float4*)buf1, edge_src,
                                            edge_weight, (float4*)buf0, co, n_nodes);
        spmm_q_kernel<1><<<spmm_grid, 64>>>((const float4*)buf0, edge_src,
                                            edge_weight, (float4*)out, co, n_nodes);
    }
}

// round 12
// speedup vs baseline: 1.0444x; 1.0444x over previous
#include <cuda_runtime.h>
#include <cuda_bf16.h>
#include <cstdint>

#define D_DIM 512
#define D_VEC 128   // D_DIM / 4 (float4 stride per row)
#define MAX_NODES 100000
#define M_TILES 782

// ---------------------------------------------------------------------------
// Scratch (allocation-free rule: device globals are allowed)
// ---------------------------------------------------------------------------
__device__ float g_buf0[(size_t)MAX_NODES * D_DIM];
__device__ float g_buf1[(size_t)MAX_NODES * D_DIM];
__device__ int   g_rowstart[MAX_NODES + 1];
// W^T bf16 hi/lo splits (small: 512x512)
__device__ uint4 g_bhi4[D_DIM * 64];             // W^T: [n][k] bf16
__device__ uint4 g_blo4[D_DIM * 64];

// ---------------------------------------------------------------------------
// PTX helpers (sm_103-safe: HMMA mma.sync + cp.async only, no tcgen05)
// ---------------------------------------------------------------------------
__device__ __forceinline__ uint32_t smem_to_u32(const void* p) {
    uint32_t a;
    asm("{ .reg .u64 t; cvta.to.shared.u64 t, %1; cvt.u32.u64 %0, t; }"
        : "=r"(a) : "l"(p));
    return a;
}
__device__ __forceinline__ void cp16(uint32_t s, const void* g) {
    asm volatile("cp.async.cg.shared.global [%0], [%1], 16;"
                 :: "r"(s), "l"(g) : "memory");
}
#define CP_COMMIT() asm volatile("cp.async.commit_group;" ::: "memory")
#define CP_WAIT(n)  asm volatile("cp.async.wait_group %0;" :: "n"(n) : "memory")

__device__ __forceinline__ uint32_t lds32(uint32_t a) {
    uint32_t v;
    asm("ld.shared.b32 %0, [%1];" : "=r"(v) : "r"(a));
    return v;
}
__device__ __forceinline__ void sts64(uint32_t a, uint32_t v0, uint32_t v1) {
    asm volatile("st.shared.v2.b32 [%0], {%1, %2};"
                 :: "r"(a), "r"(v0), "r"(v1) : "memory");
}
__device__ __forceinline__ void mma16816(float* d, const uint32_t* a,
                                         const uint32_t* b) {
    asm volatile(
        "mma.sync.aligned.m16n8k16.row.col.f32.bf16.bf16.f32 "
        "{%0,%1,%2,%3}, {%4,%5,%6,%7}, {%8,%9}, {%0,%1,%2,%3};"
        : "+f"(d[0]), "+f"(d[1]), "+f"(d[2]), "+f"(d[3])
        : "r"(a[0]), "r"(a[1]), "r"(a[2]), "r"(a[3]),
          "r"(b[0]), "r"(b[1]));
}

// ---------------------------------------------------------------------------
// Conversion: W fp32 -> (bf16 hi, bf16 lo) transposed splits (1 MB, tiny)
// ---------------------------------------------------------------------------
__global__ void convert_w_kernel(const float* __restrict__ W)
{
    int i = blockIdx.x * blockDim.x + threadIdx.x;   // over k*512+n
    if (i >= D_DIM * D_DIM) return;
    int k = i / D_DIM, n = i % D_DIM;
    float w = W[i];
    __nv_bfloat16 h = __float2bfloat16_rn(w);
    __nv_bfloat16 l = __float2bfloat16_rn(w - __bfloat162float(h));
    reinterpret_cast<__nv_bfloat16*>(g_bhi4)[n * D_DIM + k] = h;
    reinterpret_cast<__nv_bfloat16*>(g_blo4)[n * D_DIM + k] = l;
}

// ---------------------------------------------------------------------------
// HMMA GEMM with FUSED A-conversion:
//   C = Ahi·Bhi + Ahi·Blo + Alo·Bhi  (fp32 accum)
// A loaded fp32 straight from `features` (LDG float4, register double-buffer),
// converted in-register to bf16 hi/lo, STS'd into the SW-padded smem tiles.
// B (prepacked bf16 hi/lo of W^T) via cp.async double buffer.
// CTA tile 128x128, BK=32(bf16), 8 warps (2m x 4n), warp tile 64x32.
// ---------------------------------------------------------------------------
#define NCHUNKS (D_DIM / 32)   // 16
#define ROWB 80                // 32 bf16 (64B) + 16B pad
#define MATB (128 * ROWB)
#define AHI_OFF 0
#define ALO_OFF (1 * MATB)
#define BHI_OFF (2 * MATB)
#define BLO_OFF (3 * MATB)
#define BUFB (4 * MATB)
#define GEMM_SMEM (2 * BUFB)   // 81920 B

__device__ __forceinline__ void load_b_chunk(uint32_t buf, int bn, int kc, int tid)
{
    #pragma unroll
    for (int p = 0; p < 2; p++) {
        int u = tid + p * 256;          // 0..511
        int row = u >> 2, seg = u & 3;  // 128 rows x 4 segs (16B)
        uint32_t so = buf + row * ROWB + seg * 16;
        size_t gb = (size_t)(bn + row) * 64 + kc * 4 + seg;
        cp16(so + BHI_OFF, &g_bhi4[gb]);
        cp16(so + BLO_OFF, &g_blo4[gb]);
    }
}

__device__ __forceinline__ void load_a_regs(float4* pa, const float4* A,
                                            int bm, int kc, int tid, int m)
{
    #pragma unroll
    for (int p = 0; p < 4; p++) {
        int u = tid + p * 256;          // 0..1023
        int row = u >> 3, col4 = u & 7; // 128 rows x 8 float4
        int gr = bm + row;
        pa[p] = (gr < m)
            ? __ldg(&A[(size_t)gr * D_VEC + kc * 8 + col4])
            : make_float4(0.f, 0.f, 0.f, 0.f);
    }
}

__device__ __forceinline__ void store_a_smem(uint32_t buf, const float4* pa,
                                             int tid)
{
    #pragma unroll
    for (int p = 0; p < 4; p++) {
        int u = tid + p * 256;
        int row = u >> 3, col4 = u & 7;
        uint32_t so = buf + (uint32_t)(row * ROWB + col4 * 8);
        float4 v = pa[p];
        __nv_bfloat162 h01 = __floats2bfloat162_rn(v.x, v.y);
        __nv_bfloat162 h23 = __floats2bfloat162_rn(v.z, v.w);
        float lx = v.x - __bfloat162float(h01.x);
        float ly = v.y - __bfloat162float(h01.y);
        float lz = v.z - __bfloat162float(h23.x);
        float lw = v.w - __bfloat162float(h23.y);
        __nv_bfloat162 l01 = __floats2bfloat162_rn(lx, ly);
        __nv_bfloat162 l23 = __floats2bfloat162_rn(lz, lw);
        sts64(so + AHI_OFF, *reinterpret_cast<uint32_t*>(&h01),
                            *reinterpret_cast<uint32_t*>(&h23));
        sts64(so + ALO_OFF, *reinterpret_cast<uint32_t*>(&l01),
                            *reinterpret_cast<uint32_t*>(&l23));
    }
}

__global__ __launch_bounds__(256, 2) void gemm_mma_kernel(
    const float4* __restrict__ A, float* __restrict__ C, int m)
{
    extern __shared__ char smem[];
    uint32_t sb = smem_to_u32(smem);
    int tid = threadIdx.x;
    int wid = tid >> 5, lane = tid & 31;
    int wm = wid & 1, wn = wid >> 1;
    int g = lane >> 2, tig = lane & 3;
    int bn = blockIdx.x * 128;
    int bm = blockIdx.y * 128;

    float acc[4][4][4];
    #pragma unroll
    for (int i = 0; i < 4; i++)
        #pragma unroll
        for (int j = 0; j < 4; j++)
            #pragma unroll
            for (int r = 0; r < 4; r++) acc[i][j][r] = 0.f;

    float4 pa[4];
    load_a_regs(pa, A, bm, 0, tid, m);
    load_b_chunk(sb, bn, 0, tid);
    CP_COMMIT();

    for (int kc = 0; kc < NCHUNKS; kc++) {
        uint32_t cur = sb + (kc & 1) * BUFB;
        store_a_smem(cur, pa, tid);
        if (kc + 1 < NCHUNKS) {
            load_a_regs(pa, A, bm, kc + 1, tid, m);
            load_b_chunk(sb + ((kc + 1) & 1) * BUFB, bn, kc + 1, tid);
            CP_COMMIT();
            CP_WAIT(1);
        } else {
            CP_WAIT(0);
        }
        __syncthreads();

        #pragma unroll
        for (int term = 0; term < 3; term++) {
            uint32_t abase = cur + (term == 2 ? ALO_OFF : AHI_OFF);
            uint32_t bbase = cur + (term == 1 ? BLO_OFF : BHI_OFF);
            #pragma unroll
            for (int ks = 0; ks < 2; ks++) {
                uint32_t kb = (uint32_t)(ks * 32 + tig * 4);
                uint32_t afr[4][4], bfr[4][2];
                #pragma unroll
                for (int mi = 0; mi < 4; mi++) {
                    uint32_t r0 = abase + (uint32_t)((wm * 64 + mi * 16 + g) * ROWB) + kb;
                    uint32_t r1 = r0 + 8 * ROWB;
                    afr[mi][0] = lds32(r0);
                    afr[mi][1] = lds32(r1);
                    afr[mi][2] = lds32(r0 + 16);
                    afr[mi][3] = lds32(r1 + 16);
                }
                #pragma unroll
                for (int nj = 0; nj < 4; nj++) {
                    uint32_t n0 = bbase + (uint32_t)((wn * 32 + nj * 8 + g) * ROWB) + kb;
                    bfr[nj][0] = lds32(n0);
                    bfr[nj][1] = lds32(n0 + 16);
                }
                #pragma unroll
                for (int mi = 0; mi < 4; mi++)
                    #pragma unroll
                    for (int nj = 0; nj < 4; nj++)
                        mma16816(acc[mi][nj], afr[mi], bfr[nj]);
            }
        }
        __syncthreads();
    }

    #pragma unroll
    for (int mi = 0; mi < 4; mi++) {
        int r0 = bm + wm * 64 + mi * 16 + g;
        int r1 = r0 + 8;
        #pragma unroll
        for (int nj = 0; nj < 4; nj++) {
            int col = bn + wn * 32 + nj * 8 + tig * 2;
            if (r0 < m)
                *reinterpret_cast<float2*>(&C[(size_t)r0 * D_DIM + col]) =
                    make_float2(acc[mi][nj][0], acc[mi][nj][1]);
            if (r1 < m)
                *reinterpret_cast<float2*>(&C[(size_t)r1 * D_DIM + col]) =
                    make_float2(acc[mi][nj][2], acc[mi][nj][3]);
        }
    }
}

// ---------------------------------------------------------------------------
// Build row_start[] from sorted edge_dst via lower_bound binary search
// ---------------------------------------------------------------------------
__global__ void build_rowptr_kernel(const int* __restrict__ edge_dst,
                                    int n_edges, int n_nodes)
{
    int n = blockIdx.x * blockDim.x + threadIdx.x;
    if (n > n_nodes) return;
    int lo = 0, hi = n_edges;
    while (lo < hi) {
        int mid = (lo + hi) >> 1;
        if (edge_dst[mid] < n) lo = mid + 1; else hi = mid;
    }
    g_rowstart[n] = lo;
}

// ---------------------------------------------------------------------------
// SpMM quarter-column kernel (EXACT R10 form — proven fastest):
// one warp per node, 32 float4 cols, scalar edge loads, gather unroll x8.
// FINAL hop stores __stwt; intermediate hops write-back (L2-resident chain).
// ---------------------------------------------------------------------------
template <int FINAL>
__global__ __launch_bounds__(64) void spmm_q_kernel(
    const float4* __restrict__ x,
    const int*    __restrict__ edge_src,
    const float*  __restrict__ edge_weight,
    float4*       __restrict__ out,
    int col_off,     // float4 units: 0,32,64,96
    int n_nodes)
{
    int warp = threadIdx.x >> 5;
    int n = blockIdx.x * 2 + warp;
    if (n >= n_nodes) return;
    int lane = threadIdx.x & 31;
    int c = col_off + lane;
    int s = g_rowstart[n];
    int e = g_rowstart[n + 1];

    float4 acc = make_float4(0.f, 0.f, 0.f, 0.f);

    int i = s;
    for (; i + 8 <= e; i += 8) {
        int   si[8];
        float w[8];
        float4 r[8];
        #pragma unroll
        for (int j = 0; j < 8; j++) {
            si[j] = __ldcs(&edge_src[i + j]);
            w[j]  = __ldcs(&edge_weight[i + j]);
        }
        #pragma unroll
        for (int j = 0; j < 8; j++)
            r[j] = __ldg(&x[(size_t)si[j] * D_VEC + c]);
        #pragma unroll
        for (int j = 0; j < 8; j++) {
            acc.x += w[j] * r[j].x;
            acc.y += w[j] * r[j].y;
            acc.z += w[j] * r[j].z;
            acc.w += w[j] * r[j].w;
        }
    }
    if (i + 4 <= e) {
        int   si[4];
        float w[4];
        float4 r[4];
        #pragma unroll
        for (int j = 0; j < 4; j++) {
            si[j] = __ldcs(&edge_src[i + j]);
            w[j]  = __ldcs(&edge_weight[i + j]);
        }
        #pragma unroll
        for (int j = 0; j < 4; j++)
            r[j] = __ldg(&x[(size_t)si[j] * D_VEC + c]);
        #pragma unroll
        for (int j = 0; j < 4; j++) {
            acc.x += w[j] * r[j].x;
            acc.y += w[j] * r[j].y;
            acc.z += w[j] * r[j].z;
            acc.w += w[j] * r[j].w;
        }
        i += 4;
    }
    for (; i < e; i++) {
        int   sn = __ldcs(&edge_src[i]);
        float wt = __ldcs(&edge_weight[i]);
        float4 r = __ldg(&x[(size_t)sn * D_VEC + c]);
        acc.x += wt * r.x;
        acc.y += wt * r.y;
        acc.z += wt * r.z;
        acc.w += wt * r.w;
    }

    if (FINAL)
        __stwt(&out[(size_t)n * D_VEC + c], acc);
    else
        out[(size_t)n * D_VEC + c] = acc;
}

// ---------------------------------------------------------------------------
// Launch
// ---------------------------------------------------------------------------
extern "C" void kernel_launch(void* const* d_in, const int* in_sizes, int n_in,
                              void* d_out, int out_size)
{
    const float* features    = (const float*)d_in[0];
    const float* weight      = (const float*)d_in[1];
    const int*   edge_src    = (const int*)  d_in[2];
    const int*   edge_dst    = (const int*)  d_in[3];
    const float* edge_weight = (const float*)d_in[4];
    // d_in[5] = times (fixed at 3); sync read forbidden under graph capture.

    int n_nodes = in_sizes[0] / D_DIM;
    int n_edges = in_sizes[2];
    float* out = (float*)d_out;

    float* buf0 = nullptr;
    float* buf1 = nullptr;
    cudaGetSymbolAddress((void**)&buf0, g_buf0);
    cudaGetSymbolAddress((void**)&buf1, g_buf1);

    cudaFuncSetAttribute(gemm_mma_kernel,
                         cudaFuncAttributeMaxDynamicSharedMemorySize, GEMM_SMEM);

    // 1) bf16 hi/lo split of W^T only (A conversion fused into GEMM)
    convert_w_kernel<<<(D_DIM * D_DIM + 255) / 256, 256>>>(weight);

    // 2) support = features @ W via HMMA (3-term bf16 split, fused A cvt)
    dim3 gemm_grid(D_DIM / 128, M_TILES);
    gemm_mma_kernel<<<gemm_grid, 256, GEMM_SMEM>>>(
        (const float4*)features, buf0, n_nodes);

    // 3) CSR row pointers from sorted edge_dst
    build_rowptr_kernel<<<(n_nodes + 1 + 255) / 256, 256>>>(edge_dst, n_edges, n_nodes);

    // 4) 3-hop chain per column quarter (51 MB slices -> L2-resident chaining)
    int spmm_grid = (n_nodes + 1) / 2;
    for (int q = 0; q < 4; q++) {
        int co = q * 32;   // float4 column offset
        spmm_q_kernel<0><<<spmm_grid, 64>>>((const float4*)buf0, edge_src,
                                            edge_weight, (float4*)buf1, co, n_nodes);
        spmm_q_kernel<0><<<spmm_grid, 64>>>((const float4*)buf1, edge_src,
                                            edge_weight, (float4*)buf0, co, n_nodes);
        spmm_q_kernel<1><<<spmm_grid, 64>>>((const float4*)buf0, edge_src,
                                            edge_weight, (float4*)out, co, n_nodes);
    }
}

// round 14
// speedup vs baseline: 1.1324x; 1.0843x over previous
#include <cuda_runtime.h>
#include <cuda_bf16.h>
#include <cstdint>

#define D_DIM 512
#define D_VEC 128   // D_DIM / 4 (float4 stride per row)
#define MAX_NODES 100000
#define M_PAD 100096          // 782 * 128 (padded row count for GEMM tiles)
#define M_TILES 782

// ---------------------------------------------------------------------------
// Scratch (allocation-free rule: device globals are allowed)
// ---------------------------------------------------------------------------
__device__ float g_buf0[(size_t)MAX_NODES * D_DIM];
__device__ float g_buf1[(size_t)MAX_NODES * D_DIM];
__device__ int   g_rowstart[MAX_NODES + 1];
// bf16 hi/lo splits, stored as uint4 for guaranteed 16B alignment
__device__ uint4 g_ahi4[(size_t)M_PAD * 64];     // A:   [M_PAD][512] bf16
__device__ uint4 g_alo4[(size_t)M_PAD * 64];
__device__ uint4 g_bhi4[D_DIM * 64];             // W^T: [n][k] bf16
__device__ uint4 g_blo4[D_DIM * 64];

// ---------------------------------------------------------------------------
// PTX helpers (sm_103-safe: HMMA mma.sync + cp.async only, no tcgen05)
// ---------------------------------------------------------------------------
__device__ __forceinline__ uint32_t smem_to_u32(const void* p) {
    uint32_t a;
    asm("{ .reg .u64 t; cvta.to.shared.u64 t, %1; cvt.u32.u64 %0, t; }"
        : "=r"(a) : "l"(p));
    return a;
}
__device__ __forceinline__ void cp16(uint32_t s, const void* g) {
    asm volatile("cp.async.cg.shared.global [%0], [%1], 16;"
                 :: "r"(s), "l"(g) : "memory");
}
#define CP_COMMIT() asm volatile("cp.async.commit_group;" ::: "memory")
#define CP_WAIT(n)  asm volatile("cp.async.wait_group %0;" :: "n"(n) : "memory")

__device__ __forceinline__ uint32_t lds32(uint32_t a) {
    uint32_t v;
    asm("ld.shared.b32 %0, [%1];" : "=r"(v) : "r"(a));
    return v;
}
__device__ __forceinline__ void mma16816(float* d, const uint32_t* a,
                                         const uint32_t* b) {
    asm volatile(
        "mma.sync.aligned.m16n8k16.row.col.f32.bf16.bf16.f32 "
        "{%0,%1,%2,%3}, {%4,%5,%6,%7}, {%8,%9}, {%0,%1,%2,%3};"
        : "+f"(d[0]), "+f"(d[1]), "+f"(d[2]), "+f"(d[3])
        : "r"(a[0]), "r"(a[1]), "r"(a[2]), "r"(a[3]),
          "r"(b[0]), "r"(b[1]));
}

// ---------------------------------------------------------------------------
// Conversions: fp32 -> (bf16 hi, bf16 lo) splits
// ---------------------------------------------------------------------------
__global__ void convert_a_kernel(const float4* __restrict__ A, int m)
{
    size_t i = (size_t)blockIdx.x * blockDim.x + threadIdx.x;  // float4 index
    if (i >= (size_t)M_PAD * (D_DIM / 4)) return;
    size_t row = i / (D_DIM / 4);
    float4 v = make_float4(0.f, 0.f, 0.f, 0.f);
    if (row < (size_t)m) v = A[i];
    __nv_bfloat16 hx = __float2bfloat16_rn(v.x);
    __nv_bfloat16 hy = __float2bfloat16_rn(v.y);
    __nv_bfloat16 hz = __float2bfloat16_rn(v.z);
    __nv_bfloat16 hw = __float2bfloat16_rn(v.w);
    ushort4 hi, lo;
    hi.x = __bfloat16_as_ushort(hx);
    hi.y = __bfloat16_as_ushort(hy);
    hi.z = __bfloat16_as_ushort(hz);
    hi.w = __bfloat16_as_ushort(hw);
    lo.x = __bfloat16_as_ushort(__float2bfloat16_rn(v.x - __bfloat162float(hx)));
    lo.y = __bfloat16_as_ushort(__float2bfloat16_rn(v.y - __bfloat162float(hy)));
    lo.z = __bfloat16_as_ushort(__float2bfloat16_rn(v.z - __bfloat162float(hz)));
    lo.w = __bfloat16_as_ushort(__float2bfloat16_rn(v.w - __bfloat162float(hw)));
    reinterpret_cast<ushort4*>(g_ahi4)[i] = hi;
    reinterpret_cast<ushort4*>(g_alo4)[i] = lo;
}

__global__ void convert_w_kernel(const float* __restrict__ W)
{
    int i = blockIdx.x * blockDim.x + threadIdx.x;   // over k*512+n
    if (i >= D_DIM * D_DIM) return;
    int k = i / D_DIM, n = i % D_DIM;
    float w = W[i];
    __nv_bfloat16 h = __float2bfloat16_rn(w);
    __nv_bfloat16 l = __float2bfloat16_rn(w - __bfloat162float(h));
    reinterpret_cast<__nv_bfloat16*>(g_bhi4)[n * D_DIM + k] = h;
    reinterpret_cast<__nv_bfloat16*>(g_blo4)[n * D_DIM + k] = l;
}

// ---------------------------------------------------------------------------
// HMMA GEMM: C = Ahi·Bhi + Ahi·Blo + Alo·Bhi (fp32 accum) — proven R10 form
// CTA tile 128x128, BK=32, 8 warps (2m x 4n), warp tile 64x32,
// cp.async double-buffered SMEM, 80B-padded rows (conflict-free frag LDS).
// ---------------------------------------------------------------------------
#define BK 32
#define NCHUNKS (D_DIM / BK)   // 16
#define ROWB 80                // 32 bf16 (64B) + 16B pad
#define MATB (128 * ROWB)
#define AHI_OFF 0
#define ALO_OFF (1 * MATB)
#define BHI_OFF (2 * MATB)
#define BLO_OFF (3 * MATB)
#define BUFB (4 * MATB)
#define GEMM_SMEM (2 * BUFB)   // 81920 B

__device__ __forceinline__ void load_chunk(uint32_t buf, int bm, int bn,
                                           int kc, int tid)
{
    #pragma unroll
    for (int p = 0; p < 2; p++) {
        int u = tid + p * 256;
        int row = u >> 2, seg = u & 3;
        uint32_t so = buf + row * ROWB + seg * 16;
        size_t ga = (size_t)(bm + row) * 64 + kc * 4 + seg;
        size_t gb = (size_t)(bn + row) * 64 + kc * 4 + seg;
        cp16(so + AHI_OFF, &g_ahi4[ga]);
        cp16(so + ALO_OFF, &g_alo4[ga]);
        cp16(so + BHI_OFF, &g_bhi4[gb]);
        cp16(so + BLO_OFF, &g_blo4[gb]);
    }
}

__global__ __launch_bounds__(256, 2) void gemm_mma_kernel(
    float* __restrict__ C, int m)
{
    extern __shared__ char smem[];
    uint32_t sb = smem_to_u32(smem);
    int tid = threadIdx.x;
    int wid = tid >> 5, lane = tid & 31;
    int wm = wid & 1, wn = wid >> 1;
    int g = lane >> 2, tig = lane & 3;
    int bn = blockIdx.x * 128;
    int bm = blockIdx.y * 128;

    float acc[4][4][4];
    #pragma unroll
    for (int i = 0; i < 4; i++)
        #pragma unroll
        for (int j = 0; j < 4; j++)
            #pragma unroll
            for (int r = 0; r < 4; r++) acc[i][j][r] = 0.f;

    load_chunk(sb, bm, bn, 0, tid);
    CP_COMMIT();

    for (int kc = 0; kc < NCHUNKS; kc++) {
        uint32_t cur = sb + (kc & 1) * BUFB;
        if (kc + 1 < NCHUNKS) {
            load_chunk(sb + ((kc + 1) & 1) * BUFB, bm, bn, kc + 1, tid);
            CP_COMMIT();
            CP_WAIT(1);
        } else {
            CP_WAIT(0);
        }
        __syncthreads();

        #pragma unroll
        for (int term = 0; term < 3; term++) {
            uint32_t abase = cur + (term == 2 ? ALO_OFF : AHI_OFF);
            uint32_t bbase = cur + (term == 1 ? BLO_OFF : BHI_OFF);
            #pragma unroll
            for (int ks = 0; ks < 2; ks++) {
                uint32_t kb = (uint32_t)(ks * 32 + tig * 4);
                uint32_t afr[4][4], bfr[4][2];
                #pragma unroll
                for (int mi = 0; mi < 4; mi++) {
                    uint32_t r0 = abase + (uint32_t)((wm * 64 + mi * 16 + g) * ROWB) + kb;
                    uint32_t r1 = r0 + 8 * ROWB;
                    afr[mi][0] = lds32(r0);
                    afr[mi][1] = lds32(r1);
                    afr[mi][2] = lds32(r0 + 16);
                    afr[mi][3] = lds32(r1 + 16);
                }
                #pragma unroll
                for (int nj = 0; nj < 4; nj++) {
                    uint32_t n0 = bbase + (uint32_t)((wn * 32 + nj * 8 + g) * ROWB) + kb;
                    bfr[nj][0] = lds32(n0);
                    bfr[nj][1] = lds32(n0 + 16);
                }
                #pragma unroll
                for (int mi = 0; mi < 4; mi++)
                    #pragma unroll
                    for (int nj = 0; nj < 4; nj++)
                        mma16816(acc[mi][nj], afr[mi], bfr[nj]);
            }
        }
        __syncthreads();
    }

    #pragma unroll
    for (int mi = 0; mi < 4; mi++) {
        int r0 = bm + wm * 64 + mi * 16 + g;
        int r1 = r0 + 8;
        #pragma unroll
        for (int nj = 0; nj < 4; nj++) {
            int col = bn + wn * 32 + nj * 8 + tig * 2;
            if (r0 < m)
                *reinterpret_cast<float2*>(&C[(size_t)r0 * D_DIM + col]) =
                    make_float2(acc[mi][nj][0], acc[mi][nj][1]);
            if (r1 < m)
                *reinterpret_cast<float2*>(&C[(size_t)r1 * D_DIM + col]) =
                    make_float2(acc[mi][nj][2], acc[mi][nj][3]);
        }
    }
}

// ---------------------------------------------------------------------------
// Build row_start[] from sorted edge_dst via lower_bound binary search
// ---------------------------------------------------------------------------
__global__ void build_rowptr_kernel(const int* __restrict__ edge_dst,
                                    int n_edges, int n_nodes)
{
    int n = blockIdx.x * blockDim.x + threadIdx.x;
    if (n > n_nodes) return;
    int lo = 0, hi = n_edges;
    while (lo < hi) {
        int mid = (lo + hi) >> 1;
        if (edge_dst[mid] < n) lo = mid + 1; else hi = mid;
    }
    g_rowstart[n] = lo;
}

// ---------------------------------------------------------------------------
// SpMM quarter-column kernel: one warp per node, 32 float4 cols,
// gather unroll x8. Edge metadata via plain __ldg (L1-cacheable: sequential
// stream reuses 128B lines -> ~3/4 of meta loads are L1 hits, shortening the
// gather address dependency chain vs __ldcs which always misses L1).
// FINAL hop stores __stwt; intermediate hops write-back (L2-resident chain).
// ---------------------------------------------------------------------------
template <int FINAL>
__global__ __launch_bounds__(64) void spmm_q_kernel(
    const float4* __restrict__ x,
    const int*    __restrict__ edge_src,
    const float*  __restrict__ edge_weight,
    float4*       __restrict__ out,
    int col_off,     // float4 units: 0,32,64,96
    int n_nodes)
{
    int warp = threadIdx.x >> 5;
    int n = blockIdx.x * 2 + warp;
    if (n >= n_nodes) return;
    int lane = threadIdx.x & 31;
    int c = col_off + lane;
    int s = g_rowstart[n];
    int e = g_rowstart[n + 1];

    float4 acc = make_float4(0.f, 0.f, 0.f, 0.f);

    int i = s;
    for (; i + 8 <= e; i += 8) {
        int   si[8];
        float w[8];
        float4 r[8];
        #pragma unroll
        for (int j = 0; j < 8; j++) {
            si[j] = __ldg(&edge_src[i + j]);
            w[j]  = __ldg(&edge_weight[i + j]);
        }
        #pragma unroll
        for (int j = 0; j < 8; j++)
            r[j] = __ldg(&x[(size_t)si[j] * D_VEC + c]);
        #pragma unroll
        for (int j = 0; j < 8; j++) {
            acc.x += w[j] * r[j].x;
            acc.y += w[j] * r[j].y;
            acc.z += w[j] * r[j].z;
            acc.w += w[j] * r[j].w;
        }
    }
    if (i + 4 <= e) {
        int   si[4];
        float w[4];
        float4 r[4];
        #pragma unroll
        for (int j = 0; j < 4; j++) {
            si[j] = __ldg(&edge_src[i + j]);
            w[j]  = __ldg(&edge_weight[i + j]);
        }
        #pragma unroll
        for (int j = 0; j < 4; j++)
            r[j] = __ldg(&x[(size_t)si[j] * D_VEC + c]);
        #pragma unroll
        for (int j = 0; j < 4; j++) {
            acc.x += w[j] * r[j].x;
            acc.y += w[j] * r[j].y;
            acc.z += w[j] * r[j].z;
            acc.w += w[j] * r[j].w;
        }
        i += 4;
    }
    for (; i < e; i++) {
        int   sn = __ldg(&edge_src[i]);
        float wt = __ldg(&edge_weight[i]);
        float4 r = __ldg(&x[(size_t)sn * D_VEC + c]);
        acc.x += wt * r.x;
        acc.y += wt * r.y;
        acc.z += wt * r.z;
        acc.w += wt * r.w;
    }

    if (FINAL)
        __stwt(&out[(size_t)n * D_VEC + c], acc);
    else
        out[(size_t)n * D_VEC + c] = acc;
}

// ---------------------------------------------------------------------------
// Launch
// ---------------------------------------------------------------------------
extern "C" void kernel_launch(void* const* d_in, const int* in_sizes, int n_in,
                              void* d_out, int out_size)
{
    const float* features    = (const float*)d_in[0];
    const float* weight      = (const float*)d_in[1];
    const int*   edge_src    = (const int*)  d_in[2];
    const int*   edge_dst    = (const int*)  d_in[3];
    const float* edge_weight = (const float*)d_in[4];
    // d_in[5] = times (fixed at 3); sync read forbidden under graph capture.

    int n_nodes = in_sizes[0] / D_DIM;
    int n_edges = in_sizes[2];
    float* out = (float*)d_out;

    float* buf0 = nullptr;
    float* buf1 = nullptr;
    cudaGetSymbolAddress((void**)&buf0, g_buf0);
    cudaGetSymbolAddress((void**)&buf1, g_buf1);

    cudaFuncSetAttribute(gemm_mma_kernel,
                         cudaFuncAttributeMaxDynamicSharedMemorySize, GEMM_SMEM);

    // 1) bf16 hi/lo splits of features and W^T
    {
        size_t nv = (size_t)M_PAD * (D_DIM / 4);
        convert_a_kernel<<<(unsigned)((nv + 255) / 256), 256>>>(
            (const float4*)features, n_nodes);
        convert_w_kernel<<<(D_DIM * D_DIM + 255) / 256, 256>>>(weight);
    }

    // 2) support = features @ W via HMMA (3-term bf16 split) -> buf0
    dim3 gemm_grid(D_DIM / 128, M_TILES);
    gemm_mma_kernel<<<gemm_grid, 256, GEMM_SMEM>>>(buf0, n_nodes);

    // 3) CSR row pointers from sorted edge_dst
    build_rowptr_kernel<<<(n_nodes + 1 + 255) / 256, 256>>>(edge_dst, n_edges, n_nodes);

    // 4) 3-hop chain per column quarter (51 MB slices -> L2-resident chaining)
    int spmm_grid = (n_nodes + 1) / 2;
    for (int q = 0; q < 4; q++) {
        int co = q * 32;   // float4 column offset
        spmm_q_kernel<0><<<spmm_grid, 64>>>((const float4*)buf0, edge_src,
                                            edge_weight, (float4*)buf1, co, n_nodes);
        spmm_q_kernel<0><<<spmm_grid, 64>>>((const float4*)buf1, edge_src,
                                            edge_weight, (float4*)buf0, co, n_nodes);
        spmm_q_kernel<1><<<spmm_grid, 64>>>((const float4*)buf0, edge_src,
                                            edge_weight, (float4*)out, co, n_nodes);
    }
}

// round 15
// speedup vs baseline: 1.1644x; 1.0283x over previous
#include <cuda_runtime.h>
#include <cuda_bf16.h>
#include <cstdint>

#define D_DIM 512
#define D_VEC 128   // D_DIM / 4 (float4 stride per row)
#define MAX_NODES 100000
#define M_PAD 100096          // 782 * 128 (padded row count for GEMM tiles)
#define M_TILES 782

// ---------------------------------------------------------------------------
// Scratch (allocation-free rule: device globals are allowed)
// ---------------------------------------------------------------------------
__device__ float g_buf0[(size_t)MAX_NODES * D_DIM];
__device__ float g_buf1[(size_t)MAX_NODES * D_DIM];
__device__ int   g_rowstart[MAX_NODES + 1];
// bf16 hi/lo splits, stored as uint4 for guaranteed 16B alignment
__device__ uint4 g_ahi4[(size_t)M_PAD * 64];     // A:   [M_PAD][512] bf16
__device__ uint4 g_alo4[(size_t)M_PAD * 64];
__device__ uint4 g_bhi4[D_DIM * 64];             // W^T: [n][k] bf16
__device__ uint4 g_blo4[D_DIM * 64];

// ---------------------------------------------------------------------------
// PTX helpers (sm_103-safe: HMMA mma.sync + cp.async only, no tcgen05)
// ---------------------------------------------------------------------------
__device__ __forceinline__ uint32_t smem_to_u32(const void* p) {
    uint32_t a;
    asm("{ .reg .u64 t; cvta.to.shared.u64 t, %1; cvt.u32.u64 %0, t; }"
        : "=r"(a) : "l"(p));
    return a;
}
__device__ __forceinline__ void cp16(uint32_t s, const void* g) {
    asm volatile("cp.async.cg.shared.global [%0], [%1], 16;"
                 :: "r"(s), "l"(g) : "memory");
}
#define CP_COMMIT() asm volatile("cp.async.commit_group;" ::: "memory")
#define CP_WAIT(n)  asm volatile("cp.async.wait_group %0;" :: "n"(n) : "memory")

__device__ __forceinline__ uint32_t lds32(uint32_t a) {
    uint32_t v;
    asm("ld.shared.b32 %0, [%1];" : "=r"(v) : "r"(a));
    return v;
}
__device__ __forceinline__ void mma16816(float* d, const uint32_t* a,
                                         const uint32_t* b) {
    asm volatile(
        "mma.sync.aligned.m16n8k16.row.col.f32.bf16.bf16.f32 "
        "{%0,%1,%2,%3}, {%4,%5,%6,%7}, {%8,%9}, {%0,%1,%2,%3};"
        : "+f"(d[0]), "+f"(d[1]), "+f"(d[2]), "+f"(d[3])
        : "r"(a[0]), "r"(a[1]), "r"(a[2]), "r"(a[3]),
          "r"(b[0]), "r"(b[1]));
}

// ---------------------------------------------------------------------------
// Conversions: fp32 -> (bf16 hi, bf16 lo) splits
// ---------------------------------------------------------------------------
__global__ void convert_a_kernel(const float4* __restrict__ A, int m)
{
    size_t i = (size_t)blockIdx.x * blockDim.x + threadIdx.x;  // float4 index
    if (i >= (size_t)M_PAD * (D_DIM / 4)) return;
    size_t row = i / (D_DIM / 4);
    float4 v = make_float4(0.f, 0.f, 0.f, 0.f);
    if (row < (size_t)m) v = A[i];
    __nv_bfloat16 hx = __float2bfloat16_rn(v.x);
    __nv_bfloat16 hy = __float2bfloat16_rn(v.y);
    __nv_bfloat16 hz = __float2bfloat16_rn(v.z);
    __nv_bfloat16 hw = __float2bfloat16_rn(v.w);
    ushort4 hi, lo;
    hi.x = __bfloat16_as_ushort(hx);
    hi.y = __bfloat16_as_ushort(hy);
    hi.z = __bfloat16_as_ushort(hz);
    hi.w = __bfloat16_as_ushort(hw);
    lo.x = __bfloat16_as_ushort(__float2bfloat16_rn(v.x - __bfloat162float(hx)));
    lo.y = __bfloat16_as_ushort(__float2bfloat16_rn(v.y - __bfloat162float(hy)));
    lo.z = __bfloat16_as_ushort(__float2bfloat16_rn(v.z - __bfloat162float(hz)));
    lo.w = __bfloat16_as_ushort(__float2bfloat16_rn(v.w - __bfloat162float(hw)));
    reinterpret_cast<ushort4*>(g_ahi4)[i] = hi;
    reinterpret_cast<ushort4*>(g_alo4)[i] = lo;
}

__global__ void convert_w_kernel(const float* __restrict__ W)
{
    int i = blockIdx.x * blockDim.x + threadIdx.x;   // over k*512+n
    if (i >= D_DIM * D_DIM) return;
    int k = i / D_DIM, n = i % D_DIM;
    float w = W[i];
    __nv_bfloat16 h = __float2bfloat16_rn(w);
    __nv_bfloat16 l = __float2bfloat16_rn(w - __bfloat162float(h));
    reinterpret_cast<__nv_bfloat16*>(g_bhi4)[n * D_DIM + k] = h;
    reinterpret_cast<__nv_bfloat16*>(g_blo4)[n * D_DIM + k] = l;
}

// ---------------------------------------------------------------------------
// HMMA GEMM: C = Ahi·Bhi + Ahi·Blo + Alo·Bhi (fp32 accum)
// CTA tile 128x128, BK=32, 4 warps (2m x 2n), warp tile 64x64 (cuts smem
// fragment duplication 48KB -> 32KB per term-chunk vs the 2x4 warp grid),
// cp.async double-buffered SMEM, 80B-padded rows (conflict-free frag LDS).
// 2 CTAs/SM (128 thr, 80KB smem each).
// ---------------------------------------------------------------------------
#define BK 32
#define NCHUNKS (D_DIM / BK)   // 16
#define ROWB 80                // 32 bf16 (64B) + 16B pad
#define MATB (128 * ROWB)
#define AHI_OFF 0
#define ALO_OFF (1 * MATB)
#define BHI_OFF (2 * MATB)
#define BLO_OFF (3 * MATB)
#define BUFB (4 * MATB)
#define GEMM_SMEM (2 * BUFB)   // 81920 B

__device__ __forceinline__ void load_chunk(uint32_t buf, int bm, int bn,
                                           int kc, int tid)
{
    #pragma unroll
    for (int p = 0; p < 4; p++) {
        int u = tid + p * 128;          // 0..511
        int row = u >> 2, seg = u & 3;  // 128 rows x 4 segs (16B each)
        uint32_t so = buf + row * ROWB + seg * 16;
        size_t ga = (size_t)(bm + row) * 64 + kc * 4 + seg;
        size_t gb = (size_t)(bn + row) * 64 + kc * 4 + seg;
        cp16(so + AHI_OFF, &g_ahi4[ga]);
        cp16(so + ALO_OFF, &g_alo4[ga]);
        cp16(so + BHI_OFF, &g_bhi4[gb]);
        cp16(so + BLO_OFF, &g_blo4[gb]);
    }
}

__global__ __launch_bounds__(128, 2) void gemm_mma_kernel(
    float* __restrict__ C, int m)
{
    extern __shared__ char smem[];
    uint32_t sb = smem_to_u32(smem);
    int tid = threadIdx.x;
    int wid = tid >> 5, lane = tid & 31;
    int wm = wid & 1, wn = wid >> 1;        // warp grid 2m x 2n
    int g = lane >> 2, tig = lane & 3;
    int bn = blockIdx.x * 128;              // n fastest -> A stripe L2 reuse
    int bm = blockIdx.y * 128;

    float acc[4][8][4];
    #pragma unroll
    for (int i = 0; i < 4; i++)
        #pragma unroll
        for (int j = 0; j < 8; j++)
            #pragma unroll
            for (int r = 0; r < 4; r++) acc[i][j][r] = 0.f;

    load_chunk(sb, bm, bn, 0, tid);
    CP_COMMIT();

    for (int kc = 0; kc < NCHUNKS; kc++) {
        uint32_t cur = sb + (kc & 1) * BUFB;
        if (kc + 1 < NCHUNKS) {
            load_chunk(sb + ((kc + 1) & 1) * BUFB, bm, bn, kc + 1, tid);
            CP_COMMIT();
            CP_WAIT(1);
        } else {
            CP_WAIT(0);
        }
        __syncthreads();

        #pragma unroll
        for (int term = 0; term < 3; term++) {
            uint32_t abase = cur + (term == 2 ? ALO_OFF : AHI_OFF);
            uint32_t bbase = cur + (term == 1 ? BLO_OFF : BHI_OFF);
            #pragma unroll
            for (int ks = 0; ks < 2; ks++) {
                uint32_t kb = (uint32_t)(ks * 32 + tig * 4);
                uint32_t afr[4][4], bfr[8][2];
                #pragma unroll
                for (int mi = 0; mi < 4; mi++) {
                    uint32_t r0 = abase + (uint32_t)((wm * 64 + mi * 16 + g) * ROWB) + kb;
                    uint32_t r1 = r0 + 8 * ROWB;
                    afr[mi][0] = lds32(r0);
                    afr[mi][1] = lds32(r1);
                    afr[mi][2] = lds32(r0 + 16);
                    afr[mi][3] = lds32(r1 + 16);
                }
                #pragma unroll
                for (int nj = 0; nj < 8; nj++) {
                    uint32_t n0 = bbase + (uint32_t)((wn * 64 + nj * 8 + g) * ROWB) + kb;
                    bfr[nj][0] = lds32(n0);
                    bfr[nj][1] = lds32(n0 + 16);
                }
                #pragma unroll
                for (int mi = 0; mi < 4; mi++)
                    #pragma unroll
                    for (int nj = 0; nj < 8; nj++)
                        mma16816(acc[mi][nj], afr[mi], bfr[nj]);
            }
        }
        __syncthreads();
    }

    // Epilogue: direct float2 stores (full 32B sectors per row-quad)
    #pragma unroll
    for (int mi = 0; mi < 4; mi++) {
        int r0 = bm + wm * 64 + mi * 16 + g;
        int r1 = r0 + 8;
        #pragma unroll
        for (int nj = 0; nj < 8; nj++) {
            int col = bn + wn * 64 + nj * 8 + tig * 2;
            if (r0 < m)
                *reinterpret_cast<float2*>(&C[(size_t)r0 * D_DIM + col]) =
                    make_float2(acc[mi][nj][0], acc[mi][nj][1]);
            if (r1 < m)
                *reinterpret_cast<float2*>(&C[(size_t)r1 * D_DIM + col]) =
                    make_float2(acc[mi][nj][2], acc[mi][nj][3]);
        }
    }
}

// ---------------------------------------------------------------------------
// Build row_start[] from sorted edge_dst via lower_bound binary search
// ---------------------------------------------------------------------------
__global__ void build_rowptr_kernel(const int* __restrict__ edge_dst,
                                    int n_edges, int n_nodes)
{
    int n = blockIdx.x * blockDim.x + threadIdx.x;
    if (n > n_nodes) return;
    int lo = 0, hi = n_edges;
    while (lo < hi) {
        int mid = (lo + hi) >> 1;
        if (edge_dst[mid] < n) lo = mid + 1; else hi = mid;
    }
    g_rowstart[n] = lo;
}

// ---------------------------------------------------------------------------
// SpMM quarter-column kernel (proven R14 form): one warp per node,
// 32 float4 cols, gather unroll x8, meta via plain __ldg (L1-cached).
// FINAL hop stores __stwt; intermediate hops write-back (L2-resident chain).
// ---------------------------------------------------------------------------
template <int FINAL>
__global__ __launch_bounds__(64) void spmm_q_kernel(
    const float4* __restrict__ x,
    const int*    __restrict__ edge_src,
    const float*  __restrict__ edge_weight,
    float4*       __restrict__ out,
    int col_off,     // float4 units: 0,32,64,96
    int n_nodes)
{
    int warp = threadIdx.x >> 5;
    int n = blockIdx.x * 2 + warp;
    if (n >= n_nodes) return;
    int lane = threadIdx.x & 31;
    int c = col_off + lane;
    int s = g_rowstart[n];
    int e = g_rowstart[n + 1];

    float4 acc = make_float4(0.f, 0.f, 0.f, 0.f);

    int i = s;
    for (; i + 8 <= e; i += 8) {
        int   si[8];
        float w[8];
        float4 r[8];
        #pragma unroll
        for (int j = 0; j < 8; j++) {
            si[j] = __ldg(&edge_src[i + j]);
            w[j]  = __ldg(&edge_weight[i + j]);
        }
        #pragma unroll
        for (int j = 0; j < 8; j++)
            r[j] = __ldg(&x[(size_t)si[j] * D_VEC + c]);
        #pragma unroll
        for (int j = 0; j < 8; j++) {
            acc.x += w[j] * r[j].x;
            acc.y += w[j] * r[j].y;
            acc.z += w[j] * r[j].z;
            acc.w += w[j] * r[j].w;
        }
    }
    if (i + 4 <= e) {
        int   si[4];
        float w[4];
        float4 r[4];
        #pragma unroll
        for (int j = 0; j < 4; j++) {
            si[j] = __ldg(&edge_src[i + j]);
            w[j]  = __ldg(&edge_weight[i + j]);
        }
        #pragma unroll
        for (int j = 0; j < 4; j++)
            r[j] = __ldg(&x[(size_t)si[j] * D_VEC + c]);
        #pragma unroll
        for (int j = 0; j < 4; j++) {
            acc.x += w[j] * r[j].x;
            acc.y += w[j] * r[j].y;
            acc.z += w[j] * r[j].z;
            acc.w += w[j] * r[j].w;
        }
        i += 4;
    }
    for (; i < e; i++) {
        int   sn = __ldg(&edge_src[i]);
        float wt = __ldg(&edge_weight[i]);
        float4 r = __ldg(&x[(size_t)sn * D_VEC + c]);
        acc.x += wt * r.x;
        acc.y += wt * r.y;
        acc.z += wt * r.z;
        acc.w += wt * r.w;
    }

    if (FINAL)
        __stwt(&out[(size_t)n * D_VEC + c], acc);
    else
        out[(size_t)n * D_VEC + c] = acc;
}

// ---------------------------------------------------------------------------
// Launch
// ---------------------------------------------------------------------------
extern "C" void kernel_launch(void* const* d_in, const int* in_sizes, int n_in,
                              void* d_out, int out_size)
{
    const float* features    = (const float*)d_in[0];
    const float* weight      = (const float*)d_in[1];
    const int*   edge_src    = (const int*)  d_in[2];
    const int*   edge_dst    = (const int*)  d_in[3];
    const float* edge_weight = (const float*)d_in[4];
    // d_in[5] = times (fixed at 3); sync read forbidden under graph capture.

    int n_nodes = in_sizes[0] / D_DIM;
    int n_edges = in_sizes[2];
    float* out = (float*)d_out;

    float* buf0 = nullptr;
    float* buf1 = nullptr;
    cudaGetSymbolAddress((void**)&buf0, g_buf0);
    cudaGetSymbolAddress((void**)&buf1, g_buf1);

    cudaFuncSetAttribute(gemm_mma_kernel,
                         cudaFuncAttributeMaxDynamicSharedMemorySize, GEMM_SMEM);

    // 1) bf16 hi/lo splits of features and W^T
    {
        size_t nv = (size_t)M_PAD * (D_DIM / 4);
        convert_a_kernel<<<(unsigned)((nv + 255) / 256), 256>>>(
            (const float4*)features, n_nodes);
        convert_w_kernel<<<(D_DIM * D_DIM + 255) / 256, 256>>>(weight);
    }

    // 2) support = features @ W via HMMA (3-term bf16 split) -> buf0
    dim3 gemm_grid(D_DIM / 128, M_TILES);
    gemm_mma_kernel<<<gemm_grid, 128, GEMM_SMEM>>>(buf0, n_nodes);

    // 3) CSR row pointers from sorted edge_dst
    build_rowptr_kernel<<<(n_nodes + 1 + 255) / 256, 256>>>(edge_dst, n_edges, n_nodes);

    // 4) 3-hop chain per column quarter (51 MB slices -> L2-resident chaining)
    int spmm_grid = (n_nodes + 1) / 2;
    for (int q = 0; q < 4; q++) {
        int co = q * 32;   // float4 column offset
        spmm_q_kernel<0><<<spmm_grid, 64>>>((const float4*)buf0, edge_src,
                                            edge_weight, (float4*)buf1, co, n_nodes);
        spmm_q_kernel<0><<<spmm_grid, 64>>>((const float4*)buf1, edge_src,
                                            edge_weight, (float4*)buf0, co, n_nodes);
        spmm_q_kernel<1><<<spmm_grid, 64>>>((const float4*)buf0, edge_src,
                                            edge_weight, (float4*)out, co, n_nodes);
    }
}

// round 16
// speedup vs baseline: 1.3240x; 1.1371x over previous
#include <cuda_runtime.h>
#include <cuda_bf16.h>
#include <cstdint>

#define D_DIM 512
#define D_VEC 128   // D_DIM / 4 (float4 stride per row)
#define MAX_NODES 100000
#define M_TILES 782

// ---------------------------------------------------------------------------
// Scratch (allocation-free rule: device globals are allowed)
// ---------------------------------------------------------------------------
__device__ float g_buf0[(size_t)MAX_NODES * D_DIM];
__device__ float g_buf1[(size_t)MAX_NODES * D_DIM];
__device__ int   g_rowstart[MAX_NODES + 1];
__device__ float g_bT[D_DIM * D_DIM];            // W^T, tf32-rounded fp32

// ---------------------------------------------------------------------------
// PTX helpers (sm_103-safe: mma.sync + cp.async only, no tcgen05)
// ---------------------------------------------------------------------------
__device__ __forceinline__ uint32_t smem_to_u32(const void* p) {
    uint32_t a;
    asm("{ .reg .u64 t; cvta.to.shared.u64 t, %1; cvt.u32.u64 %0, t; }"
        : "=r"(a) : "l"(p));
    return a;
}
__device__ __forceinline__ void cp16(uint32_t s, const void* g) {
    asm volatile("cp.async.cg.shared.global [%0], [%1], 16;"
                 :: "r"(s), "l"(g) : "memory");
}
#define CP_COMMIT() asm volatile("cp.async.commit_group;" ::: "memory")
#define CP_WAIT(n)  asm volatile("cp.async.wait_group %0;" :: "n"(n) : "memory")

__device__ __forceinline__ float lds32f(uint32_t a) {
    float v;
    asm("ld.shared.f32 %0, [%1];" : "=f"(v) : "r"(a));
    return v;
}
__device__ __forceinline__ uint32_t lds32(uint32_t a) {
    uint32_t v;
    asm("ld.shared.b32 %0, [%1];" : "=r"(v) : "r"(a));
    return v;
}
// fp32 -> tf32 (round-to-nearest-with-ties-to-away per cvt.rna)
__device__ __forceinline__ uint32_t f2tf32(float f) {
    uint32_t y;
    asm("cvt.rna.tf32.f32 %0, %1;" : "=r"(y) : "f"(f));
    return y;
}
__device__ __forceinline__ void mma1688_tf32(float* d, const uint32_t* a,
                                             const uint32_t* b) {
    asm volatile(
        "mma.sync.aligned.m16n8k8.row.col.f32.tf32.tf32.f32 "
        "{%0,%1,%2,%3}, {%4,%5,%6,%7}, {%8,%9}, {%0,%1,%2,%3};"
        : "+f"(d[0]), "+f"(d[1]), "+f"(d[2]), "+f"(d[3])
        : "r"(a[0]), "r"(a[1]), "r"(a[2]), "r"(a[3]),
          "r"(b[0]), "r"(b[1]));
}

// ---------------------------------------------------------------------------
// W transpose + tf32 rounding: g_bT[n][k] = tf32(W[k][n])   (1 MB, tiny)
// ---------------------------------------------------------------------------
__global__ void transpose_w_kernel(const float* __restrict__ W)
{
    int i = blockIdx.x * blockDim.x + threadIdx.x;   // over k*512+n
    if (i >= D_DIM * D_DIM) return;
    int k = i / D_DIM, n = i % D_DIM;
    uint32_t t = f2tf32(W[i]);
    g_bT[n * D_DIM + k] = __uint_as_float(t);
}

// ---------------------------------------------------------------------------
// tf32 HMMA GEMM: C = A @ W (single pass, fp32 accum)
// CTA tile 128x128, BK=32, 4 warps (2m x 2n), warp tile 64x64.
// A loaded fp32 DIRECTLY from features (cp.async); frags tf32-rounded
// in-register (cvt.rna). B pre-rounded in transpose kernel.
// SMEM rows 144B (128B data + 16B pad): word-stride 36 -> 4g+tig bijective
// mod 32 => conflict-free fragment LDS. Double-buffered stages.
// ---------------------------------------------------------------------------
#define NCHUNKS (D_DIM / 32)   // 16
#define ROWB 144               // 32 fp32 (128B) + 16B pad
#define TILEB (128 * ROWB)     // 18432
#define A_OFF 0
#define B_OFF TILEB
#define BUFB (2 * TILEB)       // 36864 per stage
#define GEMM_SMEM (2 * BUFB)   // 73728 B

__device__ __forceinline__ void load_chunk(char* smem, uint32_t sb, int stage,
                                           const float* __restrict__ A,
                                           int bm, int bn, int kc, int tid, int m)
{
    #pragma unroll
    for (int p = 0; p < 8; p++) {
        int u = tid + p * 128;          // 0..1023
        int row = u >> 3, seg = u & 7;  // 128 rows x 8 segs (16B each)
        int offA = stage + A_OFF + row * ROWB + seg * 16;
        int gr = bm + row;
        if (gr < m)
            cp16(sb + offA, A + (size_t)gr * D_DIM + kc * 32 + seg * 4);
        else
            *reinterpret_cast<uint4*>(smem + offA) = make_uint4(0, 0, 0, 0);
        int offB = stage + B_OFF + row * ROWB + seg * 16;
        cp16(sb + offB, g_bT + (size_t)(bn + row) * D_DIM + kc * 32 + seg * 4);
    }
}

__global__ __launch_bounds__(128, 2) void gemm_tf32_kernel(
    const float* __restrict__ A, float* __restrict__ C, int m)
{
    extern __shared__ char smem[];
    uint32_t sb = smem_to_u32(smem);
    int tid = threadIdx.x;
    int wid = tid >> 5, lane = tid & 31;
    int wm = wid & 1, wn = wid >> 1;        // warp grid 2m x 2n
    int g = lane >> 2, tig = lane & 3;
    int bn = blockIdx.x * 128;              // n fastest -> A stripe L2 reuse
    int bm = blockIdx.y * 128;

    float acc[4][8][4];
    #pragma unroll
    for (int i = 0; i < 4; i++)
        #pragma unroll
        for (int j = 0; j < 8; j++)
            #pragma unroll
            for (int r = 0; r < 4; r++) acc[i][j][r] = 0.f;

    load_chunk(smem, sb, 0, A, bm, bn, 0, tid, m);
    CP_COMMIT();

    for (int kc = 0; kc < NCHUNKS; kc++) {
        uint32_t cur = sb + (kc & 1) * BUFB;
        if (kc + 1 < NCHUNKS) {
            load_chunk(smem, sb, ((kc + 1) & 1) * BUFB, A, bm, bn, kc + 1, tid, m);
            CP_COMMIT();
            CP_WAIT(1);
        } else {
            CP_WAIT(0);
        }
        __syncthreads();

        uint32_t abase = cur + A_OFF;
        uint32_t bbase = cur + B_OFF;
        #pragma unroll
        for (int ks = 0; ks < 4; ks++) {
            uint32_t kb = (uint32_t)(ks * 32 + tig * 4);
            uint32_t afr[4][4], bfr[8][2];
            #pragma unroll
            for (int mi = 0; mi < 4; mi++) {
                uint32_t r0 = abase + (uint32_t)((wm * 64 + mi * 16 + g) * ROWB) + kb;
                uint32_t r1 = r0 + 8 * ROWB;
                afr[mi][0] = f2tf32(lds32f(r0));
                afr[mi][1] = f2tf32(lds32f(r1));
                afr[mi][2] = f2tf32(lds32f(r0 + 16));
                afr[mi][3] = f2tf32(lds32f(r1 + 16));
            }
            #pragma unroll
            for (int nj = 0; nj < 8; nj++) {
                uint32_t n0 = bbase + (uint32_t)((wn * 64 + nj * 8 + g) * ROWB) + kb;
                bfr[nj][0] = lds32(n0);        // pre-rounded tf32 bits
                bfr[nj][1] = lds32(n0 + 16);
            }
            #pragma unroll
            for (int mi = 0; mi < 4; mi++)
                #pragma unroll
                for (int nj = 0; nj < 8; nj++)
                    mma1688_tf32(acc[mi][nj], afr[mi], bfr[nj]);
        }
        __syncthreads();
    }

    // Epilogue: direct float2 stores (full 32B sectors per row-quad)
    #pragma unroll
    for (int mi = 0; mi < 4; mi++) {
        int r0 = bm + wm * 64 + mi * 16 + g;
        int r1 = r0 + 8;
        #pragma unroll
        for (int nj = 0; nj < 8; nj++) {
            int col = bn + wn * 64 + nj * 8 + tig * 2;
            if (r0 < m)
                *reinterpret_cast<float2*>(&C[(size_t)r0 * D_DIM + col]) =
                    make_float2(acc[mi][nj][0], acc[mi][nj][1]);
            if (r1 < m)
                *reinterpret_cast<float2*>(&C[(size_t)r1 * D_DIM + col]) =
                    make_float2(acc[mi][nj][2], acc[mi][nj][3]);
        }
    }
}

// ---------------------------------------------------------------------------
// Build row_start[] from sorted edge_dst via lower_bound binary search
// ---------------------------------------------------------------------------
__global__ void build_rowptr_kernel(const int* __restrict__ edge_dst,
                                    int n_edges, int n_nodes)
{
    int n = blockIdx.x * blockDim.x + threadIdx.x;
    if (n > n_nodes) return;
    int lo = 0, hi = n_edges;
    while (lo < hi) {
        int mid = (lo + hi) >> 1;
        if (edge_dst[mid] < n) lo = mid + 1; else hi = mid;
    }
    g_rowstart[n] = lo;
}

// ---------------------------------------------------------------------------
// SpMM quarter-column kernel (proven R14 form): one warp per node,
// 32 float4 cols, gather unroll x8, meta via plain __ldg (L1-cached).
// FINAL hop stores __stwt; intermediate hops write-back (L2-resident chain).
// ---------------------------------------------------------------------------
template <int FINAL>
__global__ __launch_bounds__(64) void spmm_q_kernel(
    const float4* __restrict__ x,
    const int*    __restrict__ edge_src,
    const float*  __restrict__ edge_weight,
    float4*       __restrict__ out,
    int col_off,     // float4 units: 0,32,64,96
    int n_nodes)
{
    int warp = threadIdx.x >> 5;
    int n = blockIdx.x * 2 + warp;
    if (n >= n_nodes) return;
    int lane = threadIdx.x & 31;
    int c = col_off + lane;
    int s = g_rowstart[n];
    int e = g_rowstart[n + 1];

    float4 acc = make_float4(0.f, 0.f, 0.f, 0.f);

    int i = s;
    for (; i + 8 <= e; i += 8) {
        int   si[8];
        float w[8];
        float4 r[8];
        #pragma unroll
        for (int j = 0; j < 8; j++) {
            si[j] = __ldg(&edge_src[i + j]);
            w[j]  = __ldg(&edge_weight[i + j]);
        }
        #pragma unroll
        for (int j = 0; j < 8; j++)
            r[j] = __ldg(&x[(size_t)si[j] * D_VEC + c]);
        #pragma unroll
        for (int j = 0; j < 8; j++) {
            acc.x += w[j] * r[j].x;
            acc.y += w[j] * r[j].y;
            acc.z += w[j] * r[j].z;
            acc.w += w[j] * r[j].w;
        }
    }
    if (i + 4 <= e) {
        int   si[4];
        float w[4];
        float4 r[4];
        #pragma unroll
        for (int j = 0; j < 4; j++) {
            si[j] = __ldg(&edge_src[i + j]);
            w[j]  = __ldg(&edge_weight[i + j]);
        }
        #pragma unroll
        for (int j = 0; j < 4; j++)
            r[j] = __ldg(&x[(size_t)si[j] * D_VEC + c]);
        #pragma unroll
        for (int j = 0; j < 4; j++) {
            acc.x += w[j] * r[j].x;
            acc.y += w[j] * r[j].y;
            acc.z += w[j] * r[j].z;
            acc.w += w[j] * r[j].w;
        }
        i += 4;
    }
    for (; i < e; i++) {
        int   sn = __ldg(&edge_src[i]);
        float wt = __ldg(&edge_weight[i]);
        float4 r = __ldg(&x[(size_t)sn * D_VEC + c]);
        acc.x += wt * r.x;
        acc.y += wt * r.y;
        acc.z += wt * r.z;
        acc.w += wt * r.w;
    }

    if (FINAL)
        __stwt(&out[(size_t)n * D_VEC + c], acc);
    else
        out[(size_t)n * D_VEC + c] = acc;
}

// ---------------------------------------------------------------------------
// Launch
// ---------------------------------------------------------------------------
extern "C" void kernel_launch(void* const* d_in, const int* in_sizes, int n_in,
                              void* d_out, int out_size)
{
    const float* features    = (const float*)d_in[0];
    const float* weight      = (const float*)d_in[1];
    const int*   edge_src    = (const int*)  d_in[2];
    const int*   edge_dst    = (const int*)  d_in[3];
    const float* edge_weight = (const float*)d_in[4];
    // d_in[5] = times (fixed at 3); sync read forbidden under graph capture.

    int n_nodes = in_sizes[0] / D_DIM;
    int n_edges = in_sizes[2];
    float* out = (float*)d_out;

    float* buf0 = nullptr;
    float* buf1 = nullptr;
    cudaGetSymbolAddress((void**)&buf0, g_buf0);
    cudaGetSymbolAddress((void**)&buf1, g_buf1);

    cudaFuncSetAttribute(gemm_tf32_kernel,
                         cudaFuncAttributeMaxDynamicSharedMemorySize, GEMM_SMEM);

    // 1) W^T with tf32 rounding (A is consumed fp32 directly, no convert)
    transpose_w_kernel<<<(D_DIM * D_DIM + 255) / 256, 256>>>(weight);

    // 2) support = features @ W via single-pass tf32 HMMA -> buf0
    dim3 gemm_grid(D_DIM / 128, M_TILES);
    gemm_tf32_kernel<<<gemm_grid, 128, GEMM_SMEM>>>(features, buf0, n_nodes);

    // 3) CSR row pointers from sorted edge_dst
    build_rowptr_kernel<<<(n_nodes + 1 + 255) / 256, 256>>>(edge_dst, n_edges, n_nodes);

    // 4) 3-hop chain per column quarter (51 MB slices -> L2-resident chaining)
    int spmm_grid = (n_nodes + 1) / 2;
    for (int q = 0; q < 4; q++) {
        int co = q * 32;   // float4 column offset
        spmm_q_kernel<0><<<spmm_grid, 64>>>((const float4*)buf0, edge_src,
                                            edge_weight, (float4*)buf1, co, n_nodes);
        spmm_q_kernel<0><<<spmm_grid, 64>>>((const float4*)buf1, edge_src,
                                            edge_weight, (float4*)buf0, co, n_nodes);
        spmm_q_kernel<1><<<spmm_grid, 64>>>((const float4*)buf0, edge_src,
                                            edge_weight, (float4*)out, co, n_nodes);
    }
}